// round 12
// baseline (speedup 1.0000x reference)
#include <cuda_runtime.h>
#include <cuda_fp16.h>

// RestrictedNN GB300. B=4096, NINP=4096, L0=512(G=8,H=16), L1=64, L2=8.
// k1 (2 rows/lane, 3 blocks/SM): x -> gene-folded -> h0 -> h1.
//    h0 split into two h-halves (acc0 16 regs); tanh.approx sigmoid with
//    affine folded into w1s/bias1; next-leaf x loaded after h0-half1.
//    h1: exact ex2/rcp sigmoid, stored transposed fp16 g_h1h[feature][row].
// k2 (unchanged from R11): grid 256 x 16-row blocks, 512 thr.

#define SCALE (-1.44269504f)

typedef unsigned long long u64;

__device__ __half g_h1h[(size_t)1024 * 4096];   // [feature][row], 8 MB

__device__ __forceinline__ u64 pack2(float lo, float hi) {
    u64 r; asm("mov.b64 %0, {%1, %2};" : "=l"(r) : "f"(lo), "f"(hi)); return r;
}
__device__ __forceinline__ void unpack2(u64 v, float& lo, float& hi) {
    asm("mov.b64 {%0, %1}, %2;" : "=f"(lo), "=f"(hi) : "l"(v));
}
__device__ __forceinline__ u64 ffma2(u64 a, u64 b, u64 c) {
    u64 d; asm("fma.rn.f32x2 %0, %1, %2, %3;" : "=l"(d) : "l"(a), "l"(b), "l"(c));
    return d;
}
__device__ __forceinline__ u64 add2(u64 a, u64 b) {
    u64 d; asm("add.rn.f32x2 %0, %1, %2;" : "=l"(d) : "l"(a), "l"(b));
    return d;
}
__device__ __forceinline__ float tanhap(float z) {
    float t; asm("tanh.approx.f32 %0, %1;" : "=f"(t) : "f"(z)); return t;
}
__device__ __forceinline__ u64 sig2s(u64 z) {          // z pre-scaled by -log2e
    float a, b; unpack2(z, a, b);
    float ea, eb, ra, rb;
    asm("ex2.approx.f32 %0, %1;" : "=f"(ea) : "f"(a));
    asm("ex2.approx.f32 %0, %1;" : "=f"(eb) : "f"(b));
    asm("rcp.approx.f32 %0, %1;" : "=f"(ra) : "f"(1.0f + ea));
    asm("rcp.approx.f32 %0, %1;" : "=f"(rb) : "f"(1.0f + eb));
    return pack2(ra, rb);
}

// ---------------------------------------------------------------------------
// K1: grid (8 tile-groups, 64 g), 256 threads = 8 warps; warp -> one 64-row
// tile. Lane p handles rows (tile*64+p, tile*64+p+32). 3 blocks/SM.
// ---------------------------------------------------------------------------
__global__ __launch_bounds__(256, 3) void k1(
    const float* __restrict__ x, const float* __restrict__ Wg,
    const float* __restrict__ bgp, const float* __restrict__ W0,
    const float* __restrict__ W1)
{
    __shared__ __align__(16) float w0ps[1024];    // [l][j][h] * Wg * 0.5
    __shared__ __align__(16) float bias0s[128];   // [l][h] * 0.5
    __shared__ __align__(16) float w1s[2048];     // [k][h] * 0.5 * SCALE
    __shared__ __align__(16) float bias1s[16];    // 0.5*SCALE*sum_k W1[k][h]

    const int g   = blockIdx.y;
    const int tid = threadIdx.x;

    {
        float4 v = ((const float4*)(W0 + (size_t)g * 1024))[tid];
        float wg = Wg[g * 64 + (tid >> 2)] * 0.5f;
        float4 o; o.x = v.x * wg; o.y = v.y * wg; o.z = v.z * wg; o.w = v.w * wg;
        ((float4*)w0ps)[tid] = o;
    }
    #pragma unroll
    for (int it = 0; it < 2; ++it) {
        int i4 = tid + 256 * it;
        float4 v = ((const float4*)(W1 + (size_t)g * 2048))[i4];
        const float s = 0.5f * SCALE;
        float4 o; o.x = v.x * s; o.y = v.y * s; o.z = v.z * s; o.w = v.w * s;
        ((float4*)w1s)[i4] = o;
    }
    if (tid < 128) {
        int l = tid >> 4, h = tid & 15;
        const float* bgl = bgp + g * 64 + l * 8;
        const float* w0l = W0 + (size_t)g * 1024 + l * 128 + h;
        float a = 0.f;
        #pragma unroll
        for (int j = 0; j < 8; ++j) a += bgl[j] * w0l[j * 16];
        bias0s[tid] = a * 0.5f;
    }
    __syncthreads();
    if (tid < 16) {
        float a = 0.f;
        for (int k = 0; k < 128; ++k) a += w1s[k * 16 + tid];  // already scaled
        bias1s[tid] = a;
    }
    __syncthreads();

    const int warp = tid >> 5, lane = tid & 31;
    const int tile = blockIdx.x * 8 + warp;
    const int rA = tile * 64 + lane;
    const int rB = rA + 32;
    const float* xA = x + (size_t)rA * 4096 + g * 64;
    const float* xB = x + (size_t)rB * 4096 + g * 64;

    u64 acc1[2][8];
    #pragma unroll
    for (int hp = 0; hp < 8; ++hp) {
        u64 b = ((const u64*)bias1s)[hp];
        acc1[0][hp] = b; acc1[1][hp] = b;
    }

    float xa[8], xb[8];
    {   // load leaf 0 x (latency partly covered by the staging syncthreads)
        float4 t0 = __ldg((const float4*)xA), t1 = __ldg((const float4*)xA + 1);
        xa[0]=t0.x; xa[1]=t0.y; xa[2]=t0.z; xa[3]=t0.w;
        xa[4]=t1.x; xa[5]=t1.y; xa[6]=t1.z; xa[7]=t1.w;
        t0 = __ldg((const float4*)xB); t1 = __ldg((const float4*)xB + 1);
        xb[0]=t0.x; xb[1]=t0.y; xb[2]=t0.z; xb[3]=t0.w;
        xb[4]=t1.x; xb[5]=t1.y; xb[6]=t1.z; xb[7]=t1.w;
    }

    #pragma unroll 1
    for (int l = 0; l < 8; ++l) {
        #pragma unroll
        for (int half = 0; half < 2; ++half) {
            // ---- h0 for h-pairs [half*4, half*4+4) ----
            u64 acc0[2][4];
            #pragma unroll
            for (int q = 0; q < 4; ++q) {
                u64 b = ((const u64*)bias0s)[l * 8 + half * 4 + q];
                acc0[0][q] = b; acc0[1][q] = b;
            }
            #pragma unroll
            for (int j = 0; j < 8; ++j) {
                u64 dA = pack2(xa[j], xa[j]);
                u64 dB = pack2(xb[j], xb[j]);
                const ulonglong2* wrow =
                    (const ulonglong2*)(w0ps + l * 128 + j * 16 + half * 8);
                ulonglong2 w0v = wrow[0], w1v = wrow[1];   // broadcast
                acc0[0][0] = ffma2(dA, w0v.x, acc0[0][0]);
                acc0[0][1] = ffma2(dA, w0v.y, acc0[0][1]);
                acc0[0][2] = ffma2(dA, w1v.x, acc0[0][2]);
                acc0[0][3] = ffma2(dA, w1v.y, acc0[0][3]);
                acc0[1][0] = ffma2(dB, w0v.x, acc0[1][0]);
                acc0[1][1] = ffma2(dB, w0v.y, acc0[1][1]);
                acc0[1][2] = ffma2(dB, w1v.x, acc0[1][2]);
                acc0[1][3] = ffma2(dB, w1v.y, acc0[1][3]);
            }

            // after h0-half1, x is dead: load next leaf (overlaps trans+h1)
            if (half == 1) {
                int ln = (l + 1) & 7;
                float4 t0 = __ldg((const float4*)(xA + ln * 8));
                float4 t1 = __ldg((const float4*)(xA + ln * 8) + 1);
                xa[0]=t0.x; xa[1]=t0.y; xa[2]=t0.z; xa[3]=t0.w;
                xa[4]=t1.x; xa[5]=t1.y; xa[6]=t1.z; xa[7]=t1.w;
                t0 = __ldg((const float4*)(xB + ln * 8));
                t1 = __ldg((const float4*)(xB + ln * 8) + 1);
                xb[0]=t0.x; xb[1]=t0.y; xb[2]=t0.z; xb[3]=t0.w;
                xb[4]=t1.x; xb[5]=t1.y; xb[6]=t1.z; xb[7]=t1.w;
            }

            // ---- tanh + h1 accumulate for these 4 h-pairs ----
            #pragma unroll
            for (int q = 0; q < 4; ++q) {
                u64 dk0[2], dk1[2];
                #pragma unroll
                for (int r = 0; r < 2; ++r) {
                    float a0, a1; unpack2(acc0[r][q], a0, a1);
                    float t0 = tanhap(a0), t1 = tanhap(a1);
                    dk0[r] = pack2(t0, t0); dk1[r] = pack2(t1, t1);
                }
                const int k0 = l * 16 + (half * 4 + q) * 2;
                const ulonglong2* wr0 = (const ulonglong2*)(w1s + k0 * 16);
                const ulonglong2* wr1 = (const ulonglong2*)(w1s + (k0 + 1) * 16);
                #pragma unroll
                for (int c = 0; c < 4; ++c) {
                    ulonglong2 A = wr0[c];
                    ulonglong2 B = wr1[c];
                    #pragma unroll
                    for (int r = 0; r < 2; ++r) {
                        acc1[r][c*2]   = ffma2(dk0[r], A.x, acc1[r][c*2]);
                        acc1[r][c*2+1] = ffma2(dk0[r], A.y, acc1[r][c*2+1]);
                        acc1[r][c*2]   = ffma2(dk1[r], B.x, acc1[r][c*2]);
                        acc1[r][c*2+1] = ffma2(dk1[r], B.y, acc1[r][c*2+1]);
                    }
                }
            }
        }
    }

    // finalize h1: exact sigmoid (acc1 = SCALE*z1), store transposed fp16
    #pragma unroll
    for (int r = 0; r < 2; ++r) {
        const int row = r ? rB : rA;
        #pragma unroll
        for (int hp = 0; hp < 8; ++hp) {
            u64 s = sig2s(acc1[r][hp]);
            float s0, s1; unpack2(s, s0, s1);
            g_h1h[(size_t)(g * 16 + hp * 2)     * 4096 + row] = __float2half(s0);
            g_h1h[(size_t)(g * 16 + hp * 2 + 1) * 4096 + row] = __float2half(s1);
        }
    }
}

// ---------------------------------------------------------------------------
// K2 (unchanged): grid 256 x 16 rows, 512 threads = 16 warps.
// warp w: module m=w&7, feature half (w>>3)*64. lane: row=lane&15,
// feature parity p=lane>>4 (32 features each, stride 2). shfl_xor(16) combine.
// ---------------------------------------------------------------------------
#define H2S_FLOATS (16 * 129 + 4)

__global__ __launch_bounds__(512, 2) void k2(
    const float* __restrict__ W2, const float* __restrict__ W3,
    const float* __restrict__ Wf, float* __restrict__ out)
{
    extern __shared__ __align__(16) unsigned char smraw2[];
    float* w2s   = (float*)smraw2;             // [m][k][h] * SCALE, 16384 f
    float* w3s   = w2s + 16384;                // [k][h]  * SCALE, 2048 f
    float* h2s   = w3s + 2048;                 // [row][129]
    u64*   part2 = (u64*)(h2s + H2S_FLOATS);   // [hp][m][row] = 8*8*16
    u64*   part  = part2 + 1024;               // [hp][w][row] = 8*8*16
    float* fpart = (float*)(part + 1024);      // [w][row] = 8*16

    const int tid  = threadIdx.x;
    const int warp = tid >> 5;
    const int lane = tid & 31;
    const int row  = lane & 15;
    const int par  = lane >> 4;
    const int row0 = blockIdx.x * 16;
    const int m    = warp & 7;
    const int fb   = m * 128 + (warp >> 3) * 64 + par;   // feature base, stride 2

    #pragma unroll
    for (int it = 0; it < 8; ++it) {
        int i4 = tid + 512 * it;               // 4096 float4
        float4 v = ((const float4*)W2)[i4];
        float4 o; o.x = v.x * SCALE; o.y = v.y * SCALE; o.z = v.z * SCALE; o.w = v.w * SCALE;
        ((float4*)w2s)[i4] = o;
    }
    {
        float4 v = ((const float4*)W3)[tid];   // 512 float4
        float4 o; o.x = v.x * SCALE; o.y = v.y * SCALE; o.z = v.z * SCALE; o.w = v.w * SCALE;
        ((float4*)w3s)[tid] = o;
    }
    __syncthreads();

    u64 acc[8];
    #pragma unroll
    for (int hp = 0; hp < 8; ++hp) acc[hp] = 0ull;
    {
        const __half* actc = g_h1h + (size_t)fb * 4096 + row0 + row;
        const float* wbase = w2s + fb * 16;

        float cur[8], nxt[8];
        #pragma unroll
        for (int t = 0; t < 8; ++t)
            cur[t] = __half2float(__ldg(actc + (size_t)(2 * t) * 4096));

        #pragma unroll
        for (int b = 0; b < 4; ++b) {
            if (b < 3) {
                #pragma unroll
                for (int t = 0; t < 8; ++t)
                    nxt[t] = __half2float(
                        __ldg(actc + (size_t)(2 * ((b + 1) * 8 + t)) * 4096));
            }
            #pragma unroll
            for (int t = 0; t < 8; ++t) {
                u64 d = pack2(cur[t], cur[t]);
                const ulonglong2* wr =
                    (const ulonglong2*)(wbase + 2 * (b * 8 + t) * 16);
                ulonglong2 w0 = wr[0], w1 = wr[1], w2v = wr[2], w3v = wr[3];
                acc[0] = ffma2(d, w0.x,  acc[0]);
                acc[1] = ffma2(d, w0.y,  acc[1]);
                acc[2] = ffma2(d, w1.x,  acc[2]);
                acc[3] = ffma2(d, w1.y,  acc[3]);
                acc[4] = ffma2(d, w2v.x, acc[4]);
                acc[5] = ffma2(d, w2v.y, acc[5]);
                acc[6] = ffma2(d, w3v.x, acc[6]);
                acc[7] = ffma2(d, w3v.y, acc[7]);
            }
            #pragma unroll
            for (int t = 0; t < 8; ++t) cur[t] = nxt[t];
        }
    }
    #pragma unroll
    for (int hp = 0; hp < 8; ++hp)
        acc[hp] = add2(acc[hp], __shfl_xor_sync(0xffffffffu, acc[hp], 16));

    if (warp >= 8 && par == 0) {
        #pragma unroll
        for (int hp = 0; hp < 8; ++hp)
            part2[hp * 128 + m * 16 + row] = acc[hp];
    }
    __syncthreads();

    if (warp < 8 && par == 0) {
        #pragma unroll
        for (int hp = 0; hp < 8; ++hp) {
            u64 s = sig2s(add2(acc[hp], part2[hp * 128 + m * 16 + row]));
            float s0, s1; unpack2(s, s0, s1);
            h2s[row * 129 + m * 16 + hp * 2]     = s0;
            h2s[row * 129 + m * 16 + hp * 2 + 1] = s1;
        }
    }
    __syncthreads();

    if (warp < 8) {
        u64 racc[8];
        #pragma unroll
        for (int hp = 0; hp < 8; ++hp) racc[hp] = 0ull;
        #pragma unroll
        for (int jj = 0; jj < 16; ++jj) {
            int jg = warp * 16 + jj;
            float a = h2s[row * 129 + jg];
            u64 d = pack2(a, a);
            const ulonglong2* wr = (const ulonglong2*)(w3s + jg * 16);
            ulonglong2 w0 = wr[0], w1 = wr[1], w2v = wr[2], w3v = wr[3];
            racc[0] = ffma2(d, w0.x,  racc[0]);
            racc[1] = ffma2(d, w0.y,  racc[1]);
            racc[2] = ffma2(d, w1.x,  racc[2]);
            racc[3] = ffma2(d, w1.y,  racc[3]);
            racc[4] = ffma2(d, w2v.x, racc[4]);
            racc[5] = ffma2(d, w2v.y, racc[5]);
            racc[6] = ffma2(d, w3v.x, racc[6]);
            racc[7] = ffma2(d, w3v.y, racc[7]);
        }
        if (par == 0) {
            #pragma unroll
            for (int hp = 0; hp < 8; ++hp)
                part[hp * 128 + warp * 16 + row] = racc[hp];
        }
    }
    __syncthreads();

    if (warp < 8 && par == 0) {
        u64 s = part[warp * 128 + row];
        #pragma unroll
        for (int ww = 1; ww < 8; ++ww)
            s = add2(s, part[warp * 128 + ww * 16 + row]);
        u64 sg = sig2s(s);
        float s0, s1; unpack2(sg, s0, s1);
        float c = s0 * __ldg(Wf + warp * 2) + s1 * __ldg(Wf + warp * 2 + 1);
        fpart[warp * 16 + row] = c;
    }
    __syncthreads();

    if (warp == 0 && par == 0) {
        float a = fpart[row];
        #pragma unroll
        for (int ww = 1; ww < 8; ++ww) a += fpart[ww * 16 + row];
        out[row0 + row] = a;
    }
}

static const int K2_SMEM = (16384 + 2048 + H2S_FLOATS) * 4 + 1024 * 8 + 1024 * 8 + 128 * 4;

extern "C" void kernel_launch(void* const* d_in, const int* in_sizes, int n_in,
                              void* d_out, int out_size)
{
    const float* x  = (const float*)d_in[0];
    const float* Wg = (const float*)d_in[1];
    const float* bg = (const float*)d_in[2];
    const float* W0 = (const float*)d_in[3];
    const float* W1 = (const float*)d_in[4];
    const float* W2 = (const float*)d_in[5];
    const float* W3 = (const float*)d_in[6];
    const float* Wf = (const float*)d_in[7];
    float* out = (float*)d_out;

    cudaFuncSetAttribute(k2, cudaFuncAttributeMaxDynamicSharedMemorySize, K2_SMEM);

    dim3 g1(8, 64);
    k1<<<g1, 256>>>(x, Wg, bg, W0, W1);
    k2<<<256, 512, K2_SMEM>>>(W2, W3, Wf, out);
}